// round 5
// baseline (speedup 1.0000x reference)
#include <cuda_runtime.h>
#include <cuda_bf16.h>

#define BB 64
#define TT 1024
#define DD 64
#define HH 4
#define SPLIT 4
#define RPC 256
#define STRIDE 68
#define NEGF (-4294967296.0f)

// ---------- phase-1 smem layout (floats) ----------
#define OFF_KS   0                // 256*68 = 17408
#define OFF_P4   17408            // +1024
#define OFF_ACC  18432            // +1024
#define OFF_U    19456            // +256
#define OFF_Q0   19712            // +64
#define OFF_QH   19776            // +64
#define OFF_WRED 19840            // +32
#define OFF_MH   19872            // +4
#define OFF_QM   19876            // +1
#define SMEM_FLOATS 19880
#define SMEM_BYTES (SMEM_FLOATS * 4)

// ---------- phase-2 overlay (inside dead key tile, < 14200 < 17408) ----------
#define BF_WV    0                // 4096
#define BF_FW1   4096             // 4096
#define BF_FW2   8192             // 4096
#define BF_PACC  12288            // 1024
#define BF_SSM   13312            // 256
#define BF_PART  13568            // 256
#define BF_FB1   13888            // 64
#define BF_FB2   13952            // 64
#define BF_RES   14016            // 64
#define BF_HID   14080            // 64
#define BF_MS    14144            // 16
#define BF_LS    14160            // 16
#define BF_FS    14176            // 16
#define BF_SC    14192            // 4

// cp.async helpers
#define CP_ASYNC16(dst_u32, src) \
    asm volatile("cp.async.cg.shared.global [%0], [%1], 16;" :: "r"(dst_u32), "l"(src) : "memory")
#define CP_COMMIT() asm volatile("cp.async.commit_group;" ::: "memory")
#define CP_WAIT_ALL() asm volatile("cp.async.wait_group 0;" ::: "memory")

// cross-CTA scratch + barrier
__device__ float4 g_pacc[BB * SPLIT * DD];
__device__ float  g_pm[BB * SPLIT * HH];
__device__ float  g_pl[BB * SPLIT * HH];
__device__ unsigned g_bar;   // monotonic across graph replays

__global__ __launch_bounds__(256, 2) void fused_transformer_kernel(
    const float* __restrict__ queries, const float* __restrict__ keys,
    const int* __restrict__ query_mask, const int* __restrict__ key_mask,
    const float* __restrict__ W_Q, const float* __restrict__ W_K,
    const float* __restrict__ W_V,
    const float* __restrict__ fw1, const float* __restrict__ fw2,
    const float* __restrict__ fb1, const float* __restrict__ fb2,
    float* __restrict__ out)
{
    extern __shared__ float sm[];
    const unsigned sbase = (unsigned)__cvta_generic_to_shared(sm);

    float*  ks   = sm + OFF_KS;
    float4* p4   = (float4*)(sm + OFF_P4);
    float4* accm = (float4*)(sm + OFF_ACC);
    float*  u    = sm + OFF_U;
    float*  q0   = sm + OFF_Q0;
    float*  Qh   = sm + OFF_QH;
    float*  wred = sm + OFF_WRED;
    float*  mh   = sm + OFF_MH;

    const int split = blockIdx.x;
    const int b     = blockIdx.y;
    const int t     = threadIdx.x;
    const int k0    = split * RPC;
    const int lane  = t & 31;
    const int wid   = t >> 5;

    // ======== phase 1: attention partials ========

    // key tile DMA (cp.async: no register MLP cap, overlaps u-chain below)
    {
        const float4* kg = (const float4*)(keys + ((size_t)b * TT + k0) * DD);
        #pragma unroll
        for (int i = 0; i < 16; i++) {
            int idx = t + i * 256;
            int row = idx >> 4, c = idx & 15;
            unsigned dst = sbase + (row * STRIDE + c * 4) * 4;
            CP_ASYNC16(dst, kg + idx);
        }
        CP_COMMIT();
    }
    const int kmv = key_mask[b * TT + k0 + t];
    if (t < 64) q0[t] = queries[(size_t)b * TT * DD + t];
    if (split == 0 && t >= 64 && t < 128) out[b * 64 + (t - 64)] = 0.f;
    if (t == 128) sm[OFF_QM] = (float)query_mask[b * TT];
    __syncthreads();

    // Qh = q0 @ W_Q  (W_Q demand loads overlap key DMA)
    {
        int j = t & 63, q = t >> 6;
        float a = 0.f;
        #pragma unroll
        for (int i = q * 16; i < q * 16 + 16; i++) a += q0[i] * W_Q[i * 64 + j];
        ((float*)accm)[t] = a;
    }
    __syncthreads();
    if (t < 64) {
        float* pr = (float*)accm;
        Qh[t] = pr[t] + pr[64 + t] + pr[128 + t] + pr[192 + t];
    }
    __syncthreads();

    // u[d*4+h] = 0.25 * W_K[d][h-blk] . Qh[h-blk]
    {
        int d = t & 63, h = t >> 6;
        const float4* wr  = (const float4*)(W_K + d * 64 + h * 16);
        const float4* qh4 = (const float4*)(Qh + h * 16);
        float a = 0.f;
        #pragma unroll
        for (int c = 0; c < 4; c++) {
            float4 w = wr[c]; float4 q = qh4[c];
            a += w.x * q.x + w.y * q.y + w.z * q.z + w.w * q.w;
        }
        u[d * 4 + h] = a * 0.25f;
    }
    CP_WAIT_ALL();
    __syncthreads();

    // scores for key row t, 4 heads
    float s0, s1, s2, s3;
    {
        const float4* krow = (const float4*)&ks[t * STRIDE];
        const float4* u4 = (const float4*)u;
        float a0 = 0.f, a1 = 0.f, a2 = 0.f, a3 = 0.f;
        #pragma unroll
        for (int c = 0; c < 16; c++) {
            float4 kv = krow[c];
            float4 ux = u4[4 * c + 0], uy = u4[4 * c + 1];
            float4 uz = u4[4 * c + 2], uw = u4[4 * c + 3];
            a0 += kv.x * ux.x + kv.y * uy.x + kv.z * uz.x + kv.w * uw.x;
            a1 += kv.x * ux.y + kv.y * uy.y + kv.z * uz.y + kv.w * uw.y;
            a2 += kv.x * ux.z + kv.y * uy.z + kv.z * uz.z + kv.w * uw.z;
            a3 += kv.x * ux.w + kv.y * uy.w + kv.z * uz.w + kv.w * uw.w;
        }
        bool masked = (kmv != 1) || ((k0 + t) == 0);
        s0 = masked ? NEGF : a0;
        s1 = masked ? NEGF : a1;
        s2 = masked ? NEGF : a2;
        s3 = masked ? NEGF : a3;
    }

    // block max per head
    float m0 = s0, m1 = s1, m2 = s2, m3 = s3;
    #pragma unroll
    for (int o = 16; o; o >>= 1) {
        m0 = fmaxf(m0, __shfl_xor_sync(0xffffffffu, m0, o));
        m1 = fmaxf(m1, __shfl_xor_sync(0xffffffffu, m1, o));
        m2 = fmaxf(m2, __shfl_xor_sync(0xffffffffu, m2, o));
        m3 = fmaxf(m3, __shfl_xor_sync(0xffffffffu, m3, o));
    }
    if (lane == 0) {
        wred[wid * 4 + 0] = m0; wred[wid * 4 + 1] = m1;
        wred[wid * 4 + 2] = m2; wred[wid * 4 + 3] = m3;
    }
    __syncthreads();
    if (t < 4) {
        float m = wred[t];
        #pragma unroll
        for (int w = 1; w < 8; w++) m = fmaxf(m, wred[w * 4 + t]);
        mh[t] = m;
    }
    __syncthreads();

    // p = exp(s - m); block sum
    float p0 = __expf(s0 - mh[0]);
    float p1 = __expf(s1 - mh[1]);
    float p2 = __expf(s2 - mh[2]);
    float p3 = __expf(s3 - mh[3]);
    p4[t] = make_float4(p0, p1, p2, p3);
    float l0 = p0, l1 = p1, l2 = p2, l3 = p3;
    #pragma unroll
    for (int o = 16; o; o >>= 1) {
        l0 += __shfl_xor_sync(0xffffffffu, l0, o);
        l1 += __shfl_xor_sync(0xffffffffu, l1, o);
        l2 += __shfl_xor_sync(0xffffffffu, l2, o);
        l3 += __shfl_xor_sync(0xffffffffu, l3, o);
    }
    if (lane == 0) {
        wred[wid * 4 + 0] = l0; wred[wid * 4 + 1] = l1;
        wred[wid * 4 + 2] = l2; wred[wid * 4 + 3] = l3;
    }
    __syncthreads();
    if (t < 4) {
        float l = wred[t];
        #pragma unroll
        for (int w = 1; w < 8; w++) l += wred[w * 4 + t];
        g_pm[(b * SPLIT + split) * HH + t] = mh[t];
        g_pl[(b * SPLIT + split) * HH + t] = l;
    }

    // weighted key sum
    {
        int d = t & 63, q = t >> 6;
        float ax = 0.f, ay = 0.f, az = 0.f, aw = 0.f;
        const int kb = q * 64;
        #pragma unroll 4
        for (int kk = 0; kk < 64; kk++) {
            float kv = ks[(kb + kk) * STRIDE + d];
            float4 p = p4[kb + kk];
            ax += p.x * kv; ay += p.y * kv; az += p.z * kv; aw += p.w * kv;
        }
        accm[t] = make_float4(ax, ay, az, aw);
    }
    __syncthreads();   // key tile now dead
    if (t < 64) {
        float4 a = accm[t], c = accm[64 + t], d4 = accm[128 + t], e = accm[192 + t];
        float4 r;
        r.x = a.x + c.x + d4.x + e.x;
        r.y = a.y + c.y + d4.y + e.y;
        r.z = a.z + c.z + d4.z + e.z;
        r.w = a.w + c.w + d4.w + e.w;
        g_pacc[(b * SPLIT + split) * DD + t] = r;
    }

    // ======== FFN weight prefetch into dead key-tile smem (overlaps barrier) ==
    {
        const float4* gv = (const float4*)W_V;
        const float4* g1 = (const float4*)fw1;              // row stride 64 f4
        const float4* g2 = (const float4*)(fw2 + split * 64 * 64);
        #pragma unroll
        for (int i = 0; i < 4; i++) {
            int idx = t + i * 256;
            CP_ASYNC16(sbase + BF_WV * 4 + idx * 16, gv + idx);
        }
        #pragma unroll
        for (int i = 0; i < 4; i++) {
            int idx = t + i * 256;
            int row = idx >> 4, c = idx & 15;
            CP_ASYNC16(sbase + BF_FW1 * 4 + idx * 16, g1 + row * 64 + split * 16 + c);
        }
        #pragma unroll
        for (int i = 0; i < 4; i++) {
            int idx = t + i * 256;
            CP_ASYNC16(sbase + BF_FW2 * 4 + idx * 16, g2 + idx);
        }
        if (t < 16) {
            CP_ASYNC16(sbase + BF_FB1 * 4 + t * 16, ((const float4*)fb1) + split * 16 + t);
        } else if (t < 32) {
            CP_ASYNC16(sbase + BF_FB2 * 4 + (t - 16) * 16, ((const float4*)fb2) + (t - 16));
        }
        CP_COMMIT();
    }

    // ======== grid-wide barrier (monotonic counter; graph-replay safe) ========
    __threadfence();
    __syncthreads();
    if (t == 0) {
        unsigned old = atomicAdd(&g_bar, 1u);
        unsigned target = (old & ~255u) + 256u;
        while (*(volatile unsigned*)&g_bar < target) __nanosleep(64);
        __threadfence();
    }
    __syncthreads();

    // ======== phase 2: combine + FFN slice ========
    CP_WAIT_ALL();

    float*  wv_s   = sm + BF_WV;
    float*  fw1_s  = sm + BF_FW1;
    float*  fw2_s  = sm + BF_FW2;
    float4* pacc_s = (float4*)(sm + BF_PACC);
    float*  s_sm   = sm + BF_SSM;
    float*  part_s = sm + BF_PART;
    float*  fb1_s  = sm + BF_FB1;
    float*  fb2_s  = sm + BF_FB2;
    float*  res_s  = sm + BF_RES;
    float*  hid_s  = sm + BF_HID;
    float*  m_s    = sm + BF_MS;
    float*  l_s    = sm + BF_LS;
    float*  f_s    = sm + BF_FS;
    float*  sc_s   = sm + BF_SC;

    pacc_s[t] = g_pacc[b * (SPLIT * DD) + t];
    if (t < 16) {
        m_s[t] = g_pm[b * 16 + t];
        l_s[t] = g_pl[b * 16 + t];
    }
    __syncthreads();

    if (t < HH) {
        float M = m_s[t];
        #pragma unroll
        for (int s = 1; s < SPLIT; s++) M = fmaxf(M, m_s[s * HH + t]);
        float L = 0.f;
        #pragma unroll
        for (int s = 0; s < SPLIT; s++) {
            float f = __expf(m_s[s * HH + t] - M);
            f_s[s * HH + t] = f;
            L += l_s[s * HH + t] * f;
        }
        sc_s[t] = sm[OFF_QM] / L;
    }
    __syncthreads();

    {
        int d = t & 63, h = t >> 6;
        const float* pa = (const float*)pacc_s;
        float S = 0.f;
        #pragma unroll
        for (int s = 0; s < SPLIT; s++)
            S += pa[(s * DD + d) * 4 + h] * f_s[s * HH + h];
        s_sm[h * DD + d] = S * sc_s[h];
    }
    __syncthreads();

    // res[j] = s[h(j)] @ W_V[:,j] + q0[j]
    {
        int j = t & 63, qq = t >> 6;
        int h = j >> 4;
        float a = 0.f;
        #pragma unroll
        for (int d = qq * 16; d < qq * 16 + 16; d++) a += s_sm[h * DD + d] * wv_s[d * 64 + j];
        part_s[t] = a;
    }
    __syncthreads();
    if (t < 64) {
        float o = part_s[t] + part_s[64 + t] + part_s[128 + t] + part_s[192 + t];
        res_s[t] = o + q0[t];
    }
    __syncthreads();

    // hidden slice
    {
        int m = t & 63, jq = t >> 6;
        float a = 0.f;
        #pragma unroll
        for (int j = jq * 16; j < jq * 16 + 16; j++) a += res_s[j] * fw1_s[j * 64 + m];
        part_s[t] = a;
    }
    __syncthreads();
    if (t < 64) {
        float a = part_s[t] + part_s[64 + t] + part_s[128 + t] + part_s[192 + t] + fb1_s[t];
        hid_s[t] = (a > 0.f) ? a : 0.2f * a;
    }
    __syncthreads();

    // output partial
    {
        int j = t & 63, mq = t >> 6;
        float a = 0.f;
        #pragma unroll
        for (int m2 = mq * 16; m2 < mq * 16 + 16; m2++) a += hid_s[m2] * fw2_s[m2 * 64 + j];
        part_s[t] = a;
    }
    __syncthreads();
    if (t < 64) {
        float v = part_s[t] + part_s[64 + t] + part_s[128 + t] + part_s[192 + t];
        if (split == 0) v += res_s[t] + fb2_s[t];
        atomicAdd(&out[b * 64 + t], v);
    }
}

extern "C" void kernel_launch(void* const* d_in, const int* in_sizes, int n_in,
                              void* d_out, int out_size)
{
    const float* queries = (const float*)d_in[0];
    const float* keys    = (const float*)d_in[1];
    const int*   qmask   = (const int*)d_in[2];
    const int*   kmask   = (const int*)d_in[3];
    const float* W_Q     = (const float*)d_in[4];
    const float* W_K     = (const float*)d_in[5];
    const float* W_V     = (const float*)d_in[6];
    const float* fw1     = (const float*)d_in[7];
    const float* fw2     = (const float*)d_in[8];
    const float* fb1     = (const float*)d_in[9];
    const float* fb2     = (const float*)d_in[10];
    float* out = (float*)d_out;

    cudaFuncSetAttribute(fused_transformer_kernel,
                         cudaFuncAttributeMaxDynamicSharedMemorySize, SMEM_BYTES);

    fused_transformer_kernel<<<dim3(SPLIT, BB), 256, SMEM_BYTES>>>(
        queries, keys, qmask, kmask, W_Q, W_K, W_V, fw1, fw2, fb1, fb2, out);
}